// round 9
// baseline (speedup 1.0000x reference)
#include <cuda_runtime.h>

// DimeNetPP radius-graph distances + triplet angles. Two-kernel split:
//   1) fill_kernel: saturating float4 zero-fill of the angles region only.
//   2) scatter_kernel: one warp per (molecule, center-row); no block barriers;
//      writes the full dists row + scattered triplet angles.
// Inputs: [0] atomic_ns (unused), [1] coords f32 [N,3], [2] batch_node_vec (unused)
// Output: f32, dists [B,48,48] then angles [B,48,48,48].

#define MOL_B 128
#define MM 48
#define CUTOFF_F 1.5f

#define ANG_OFF ((size_t)MOL_B * MM * MM)            // 294912 floats
#define ANG_F4  (MOL_B * MM * MM * MM / 4)           // 3,538,944 float4

#define FILL_THREADS 256
#define FILL_CTAS 1776                                // 12 * 148

__global__ __launch_bounds__(FILL_THREADS)
void fill_kernel(float4* __restrict__ p)
{
    const float4 z = make_float4(0.f, 0.f, 0.f, 0.f);
    const int stride = FILL_CTAS * FILL_THREADS;
    int i = blockIdx.x * FILL_THREADS + threadIdx.x;
    #pragma unroll 8
    for (; i < ANG_F4; i += stride) p[i] = z;
}

// Branch-free atan2 for y >= 0, (x,y) != (0,0). Max rel err ~1.3e-4.
__device__ __forceinline__ float fast_atan2_pos(float y, float x)
{
    const float ax = fabsf(x);
    const float mn = fminf(y, ax);
    const float mx = fmaxf(y, ax);
    const float t  = __fdividef(mn, mx);
    const float s  = t * t;
    float p = fmaf(s, 0.0208351f, -0.0851330f);
    p = fmaf(s, p, 0.1801410f);
    p = fmaf(s, p, -0.3302995f);
    p = fmaf(s, p, 0.9998660f);
    p = p * t;
    p = (y > ax) ? (1.57079632679f - p) : p;
    p = (x < 0.0f) ? (3.14159265359f - p) : p;
    return p;
}

#define SC_THREADS 128
#define SC_CTAS (MOL_B * MM / 4)    // 1536 CTAs, 4 warps each = 6144 rows

__global__ __launch_bounds__(SC_THREADS)
void scatter_kernel(const float* __restrict__ coords, float* __restrict__ out)
{
    const int tid  = threadIdx.x;
    const int wid  = tid >> 5;
    const int lane = tid & 31;
    const int b    = blockIdx.x / 12;                 // molecule
    const int j    = (blockIdx.x % 12) * 4 + wid;     // center row

    __shared__ float nx[4][MM], ny[4][MM], nz[4][MM], nd2[4][MM];
    __shared__ int   nk[4][MM];

    const float* __restrict__ mc = coords + b * (MM * 3);
    float* __restrict__ dists  = out;
    float* __restrict__ angles = out + ANG_OFF;

    // Center coords (uniform per warp; L1/L2 hot).
    const float px = __ldg(&mc[j * 3 + 0]);
    const float py = __ldg(&mc[j * 3 + 1]);
    const float pz = __ldg(&mc[j * 3 + 2]);
    const unsigned below = (1u << lane) - 1u;
    float* const drow = dists + ((size_t)b * MM + j) * MM;

    // chunk 0: q = lane
    const int q0 = lane;
    const float vx0 = __ldg(&mc[q0 * 3 + 0]) - px;
    const float vy0 = __ldg(&mc[q0 * 3 + 1]) - py;
    const float vz0 = __ldg(&mc[q0 * 3 + 2]) - pz;
    const float d20 = vx0 * vx0 + vy0 * vy0 + vz0 * vz0;
    const float dist0 = sqrtf(d20);
    const bool adj0 = (q0 != j) && (dist0 < CUTOFF_F);
    drow[q0] = adj0 ? dist0 : 0.0f;
    const unsigned m0 = __ballot_sync(0xffffffffu, adj0);

    // chunk 1: q = lane + 32 (lanes 0..15)
    bool adj1 = false;
    const int q1 = lane + 32;
    float vx1 = 0.f, vy1 = 0.f, vz1 = 0.f, d21 = 0.f;
    if (lane < 16) {
        vx1 = __ldg(&mc[q1 * 3 + 0]) - px;
        vy1 = __ldg(&mc[q1 * 3 + 1]) - py;
        vz1 = __ldg(&mc[q1 * 3 + 2]) - pz;
        d21 = vx1 * vx1 + vy1 * vy1 + vz1 * vz1;
        const float dist1 = sqrtf(d21);
        adj1 = (q1 != j) && (dist1 < CUTOFF_F);
        drow[q1] = adj1 ? dist1 : 0.0f;
    }
    const unsigned m1 = __ballot_sync(0xffffffffu, adj1);

    const int c0 = __popc(m0);
    const int c  = c0 + __popc(m1);
    if (adj0) {
        const int s = __popc(m0 & below);
        nx[wid][s] = vx0; ny[wid][s] = vy0; nz[wid][s] = vz0;
        nd2[wid][s] = d20; nk[wid][s] = q0;
    }
    if (adj1) {
        const int s = c0 + __popc(m1 & below);
        nx[wid][s] = vx1; ny[wid][s] = vy1; nz[wid][s] = vz1;
        nd2[wid][s] = d21; nk[wid][s] = q1;
    }
    __syncwarp();

    // Triplets for this row (~c^2 ≈ 121), warp-strided scatter.
    float* const rowbase = angles + (((size_t)b * MM + j) * MM) * MM;
    const int T = c * c;
    const float fc = (float)c;
    #pragma unroll 4
    for (int g = lane; g < T; g += 32) {
        const int pi = (int)__fdividef((float)g + 0.5f, fc);
        const int ki = g - pi * c;

        const float vix = nx[wid][pi], viy = ny[wid][pi], viz = nz[wid][pi];
        const float vkx = nx[wid][ki], vky = ny[wid][ki], vkz = nz[wid][ki];
        const float a  = vix * vkx + viy * vky + viz * vkz;
        const float b2 = fmaxf(nd2[wid][pi] * nd2[wid][ki] - a * a, 0.f);
        const float ang = fast_atan2_pos(sqrtf(b2), a);

        if (pi != ki)
            rowbase[nk[wid][pi] * MM + nk[wid][ki]] = ang;
    }
}

extern "C" void kernel_launch(void* const* d_in, const int* in_sizes, int n_in,
                              void* d_out, int out_size)
{
    const float* coords = (const float*)d_in[1];
    float* out = (float*)d_out;
    fill_kernel<<<FILL_CTAS, FILL_THREADS>>>(
        reinterpret_cast<float4*>(out + ANG_OFF));
    scatter_kernel<<<SC_CTAS, SC_THREADS>>>(coords, out);
}

// round 11
// speedup vs baseline: 1.2623x; 1.2623x over previous
#include <cuda_runtime.h>

// DimeNetPP radius-graph distances + triplet angles. Fused, warp-autonomous:
// one warp per (molecule, center-row j). Each warp zero-fills its OWN 48x48
// angle slab, builds its adjacency row + dists, then scatters only the real
// triplets -- exploiting angle(i,k)==angle(k,i) to halve the compute.
// No block barriers; __syncwarp() orders fill stores before scatter stores.
// Inputs: [0] atomic_ns (unused), [1] coords f32 [N,3], [2] batch_node_vec (unused)
// Output: f32, dists [B,48,48] then angles [B,48,48,48].

#define MOL_B 128
#define MM 48
#define THREADS 128
#define CTAS (MOL_B * MM / 4)    // 1536 CTAs x 4 warps = 6144 rows
#define CUTOFF_F 1.5f

// Branch-free atan2 for y >= 0, (x,y) != (0,0). Max rel err ~1.3e-4.
__device__ __forceinline__ float fast_atan2_pos(float y, float x)
{
    const float ax = fabsf(x);
    const float mn = fminf(y, ax);
    const float mx = fmaxf(y, ax);
    const float t  = __fdividef(mn, mx);
    const float s  = t * t;
    float p = fmaf(s, 0.0208351f, -0.0851330f);
    p = fmaf(s, p, 0.1801410f);
    p = fmaf(s, p, -0.3302995f);
    p = fmaf(s, p, 0.9998660f);
    p = p * t;
    p = (y > ax) ? (1.57079632679f - p) : p;
    p = (x < 0.0f) ? (3.14159265359f - p) : p;
    return p;
}

__global__ __launch_bounds__(THREADS)
void dimenet_kernel(const float* __restrict__ coords, float* __restrict__ out)
{
    const int tid  = threadIdx.x;
    const int wid  = tid >> 5;
    const int lane = tid & 31;
    const int b    = blockIdx.x / 12;                 // molecule
    const int j    = (blockIdx.x % 12) * 4 + wid;     // center row

    __shared__ float nx[4][MM], ny[4][MM], nz[4][MM], nd2[4][MM];
    __shared__ int   nk[4][MM];

    const float* __restrict__ mc = coords + b * (MM * 3);
    float* __restrict__ dists  = out;
    float* __restrict__ angles = out + (size_t)MOL_B * MM * MM;

    // Zero-fill this warp's own 48x48 angle slab (576 float4, 18 per lane).
    float* const rowbase = angles + (((size_t)b * MM + j) * MM) * MM;
    {
        float4* zb = reinterpret_cast<float4*>(rowbase);
        const float4 z = make_float4(0.f, 0.f, 0.f, 0.f);
        #pragma unroll
        for (int t = 0; t < 18; t++)
            zb[lane + t * 32] = z;
    }

    // Adjacency + dists row + compacted neighbor vectors (all warp-local).
    const float px = __ldg(&mc[j * 3 + 0]);
    const float py = __ldg(&mc[j * 3 + 1]);
    const float pz = __ldg(&mc[j * 3 + 2]);
    const unsigned below = (1u << lane) - 1u;
    float* const drow = dists + ((size_t)b * MM + j) * MM;

    const int q0 = lane;
    const float vx0 = __ldg(&mc[q0 * 3 + 0]) - px;
    const float vy0 = __ldg(&mc[q0 * 3 + 1]) - py;
    const float vz0 = __ldg(&mc[q0 * 3 + 2]) - pz;
    const float d20 = vx0 * vx0 + vy0 * vy0 + vz0 * vz0;
    const float dist0 = sqrtf(d20);
    const bool adj0 = (q0 != j) && (dist0 < CUTOFF_F);
    drow[q0] = adj0 ? dist0 : 0.0f;
    const unsigned m0 = __ballot_sync(0xffffffffu, adj0);

    bool adj1 = false;
    const int q1 = lane + 32;
    float vx1 = 0.f, vy1 = 0.f, vz1 = 0.f, d21 = 0.f;
    if (lane < 16) {
        vx1 = __ldg(&mc[q1 * 3 + 0]) - px;
        vy1 = __ldg(&mc[q1 * 3 + 1]) - py;
        vz1 = __ldg(&mc[q1 * 3 + 2]) - pz;
        d21 = vx1 * vx1 + vy1 * vy1 + vz1 * vz1;
        const float dist1 = sqrtf(d21);
        adj1 = (q1 != j) && (dist1 < CUTOFF_F);
        drow[q1] = adj1 ? dist1 : 0.0f;
    }
    const unsigned m1 = __ballot_sync(0xffffffffu, adj1);

    const int c0 = __popc(m0);
    const int c  = c0 + __popc(m1);
    if (adj0) {
        const int s = __popc(m0 & below);
        nx[wid][s] = vx0; ny[wid][s] = vy0; nz[wid][s] = vz0;
        nd2[wid][s] = d20; nk[wid][s] = q0;
    }
    if (adj1) {
        const int s = c0 + __popc(m1 & below);
        nx[wid][s] = vx1; ny[wid][s] = vy1; nz[wid][s] = vz1;
        nd2[wid][s] = d21; nk[wid][s] = q1;
    }

    // Orders: fill stores -> scatter stores (same addresses), and smem
    // neighbor arrays -> reads below. Single warp-level barrier.
    __syncwarp();

    // Strict upper-triangle pairs (pi > ki); write both (i,k) and (k,i).
    const int T = (c * (c - 1)) >> 1;
    #pragma unroll 2
    for (int g = lane; g < T; g += 32) {
        // pi = row of triangle index g, ki = g - pi*(pi-1)/2, with fixups.
        int pi = (int)((1.0f + sqrtf(fmaf(8.f, (float)g, 1.f))) * 0.5f);
        if ((pi * (pi - 1)) >> 1 > g) pi--;
        if ((pi * (pi + 1)) >> 1 <= g) pi++;
        const int ki = g - ((pi * (pi - 1)) >> 1);

        const float vix = nx[wid][pi], viy = ny[wid][pi], viz = nz[wid][pi];
        const float vkx = nx[wid][ki], vky = ny[wid][ki], vkz = nz[wid][ki];
        const float a  = vix * vkx + viy * vky + viz * vkz;
        const float b2 = fmaxf(nd2[wid][pi] * nd2[wid][ki] - a * a, 0.f);
        const float ang = fast_atan2_pos(sqrtf(b2), a);

        const int ii = nk[wid][pi];
        const int kk = nk[wid][ki];
        rowbase[ii * MM + kk] = ang;
        rowbase[kk * MM + ii] = ang;
    }
}

extern "C" void kernel_launch(void* const* d_in, const int* in_sizes, int n_in,
                              void* d_out, int out_size)
{
    const float* coords = (const float*)d_in[1];
    float* out = (float*)d_out;
    dimenet_kernel<<<CTAS, THREADS>>>(coords, out);
}